// round 7
// baseline (speedup 1.0000x reference)
#include <cuda_runtime.h>
#include <cuda_bf16.h>

#define BB 256
#define TT 512
#define DD 64
#define HH 128
#define NBLK 128
#define TPB 1024

// ---------------- device scratch (static, no allocation) ----------------
__device__ __nv_bfloat16 g_w1p[32 * 512 * 8];   // [kk][s][u], k = kk*8+u in [0,256)
__device__ __nv_bfloat16 g_wzp[24 * 512 * 8];   // [kk][j][u], k' in [0,192): 0..63 Wih, 64..191 Whh
__device__ unsigned g_bar_count = 0;
__device__ unsigned g_bar_flag = 0;

// ---------------- helpers ----------------
typedef unsigned long long ull;

__device__ __forceinline__ float tanh_fast(float x) {
    float y;
    asm("tanh.approx.f32 %0, %1;" : "=f"(y) : "f"(x));
    return y;
}
__device__ __forceinline__ float sigf(float x) { return 1.f / (1.f + __expf(-x)); }
__device__ __forceinline__ float tanh_ex(float x) {
    x = fminf(fmaxf(x, -15.f), 15.f);
    float e = __expf(2.f * x);
    return (e - 1.f) / (e + 1.f);
}
__device__ __forceinline__ unsigned pack_bf2(float a, float b) {
    __nv_bfloat162 t = __floats2bfloat162_rn(a, b);
    return *(unsigned*)&t;
}
__device__ __forceinline__ float bl(unsigned u) { return __uint_as_float(u << 16); }
__device__ __forceinline__ float bh(unsigned u) { return __uint_as_float(u & 0xffff0000u); }
__device__ __forceinline__ void ffma2(ull& acc, ull ab, ull cd) {
    asm("fma.rn.f32x2 %0, %1, %2, %0;" : "+l"(acc) : "l"(ab), "l"(cd));
}
__device__ __forceinline__ ull bfpair(unsigned u) {
    ull p;
    asm("{\n\t.reg .b32 lo, hi;\n\t"
        "shl.b32 lo, %1, 16;\n\t"
        "and.b32 hi, %1, 0xff" "ff0000;\n\t"
        "mov.b64 %0, {lo, hi};\n\t}" : "=l"(p) : "r"(u));
    return p;
}
__device__ __forceinline__ ull mk_pair(float lo, float hi) {
    ull p;
    asm("mov.b64 %0, {%1, %2};" : "=l"(p) : "f"(lo), "f"(hi));
    return p;
}
__device__ __forceinline__ float pair_lo(ull p) { return __uint_as_float((unsigned)p); }
__device__ __forceinline__ float pair_hi(ull p) { return __uint_as_float((unsigned)(p >> 32)); }
__device__ __forceinline__ float pair_sum(ull p) { return pair_lo(p) + pair_hi(p); }

// ---------------- smem layout ----------------
#define S2STRIDE 552                              // 1104B rows: 8 consecutive d -> 8 distinct bank offsets
#define SM_S2_BYTES (2 * 64 * S2STRIDE * 2)       // 141312
#define SM_WIH_BYTES (8 * 512 * 16)               // 65536
#define SM_FLOATS (512 + 1024 + 1024 + 1024 + 1024 + 128 + 128 + 512 + 512 + 512)  // 6400
#define SM_TOTAL (SM_S2_BYTES + SM_WIH_BYTES + SM_FLOATS * 4)                       // 232448 = 227KB

// ---------------- the one kernel ----------------
__global__ void __launch_bounds__(TPB, 1) fused_kernel(
    const float* __restrict__ din, const float* __restrict__ Wih,
    const float* __restrict__ Whh, const float* __restrict__ bih,
    const float* __restrict__ bhh, const float* __restrict__ W1,
    const float* __restrict__ b1, const float* __restrict__ W2,
    const float* __restrict__ b2, const float* __restrict__ W3,
    const float* __restrict__ b3, float* __restrict__ out) {
    extern __shared__ char smraw[];
    __nv_bfloat16* s2s = (__nv_bfloat16*)smraw;                 // [2*64][552]
    uint4* wihs = (uint4*)(smraw + SM_S2_BYTES);                // [8*512] uint4
    float* hc   = (float*)(smraw + SM_S2_BYTES + SM_WIH_BYTES); // [2][256] : h then c
    float* s1pa = hc + 512;                                      // [2][512] partial A (also zbuf)
    float* s1pb = s1pa + 1024;                                   // [2][512] partial B
    float* zhpa = s1pb + 1024;                                   // [2][512]
    float* zhpb = zhpa + 1024;                                   // [2][512]
    float* xs   = zhpb + 1024;                                   // [2][64]
    float* es   = xs + 128;                                      // [2][64]
    float* w3s  = es + 128;                                      // [512]
    float* b1s  = w3s + 512;                                     // [512]
    float* bzs  = b1s + 512;                                     // [512]
    float* zbuf = s1pa;                                          // reuse for z in phase D/E

    const int tid = threadIdx.x;
    const int b0 = blockIdx.x * 2;

    // ======== STAGE 1: pack weights (grid-strided) ========
    {
        int gidx = blockIdx.x * TPB + tid;
        int gstride = NBLK * TPB;
        for (int i = gidx; i < 32 * 512 * 8; i += gstride) {
            int u = i & 7, s = (i >> 3) & 511, kk = i >> 12;
            g_w1p[i] = __float2bfloat16(W1[s * 256 + kk * 8 + u]);
        }
        for (int i = gidx; i < 24 * 512 * 8; i += gstride) {
            int u = i & 7, j = (i >> 3) & 511, kk = i >> 12;
            int k = kk * 8 + u;
            float v = (k < 64) ? Wih[j * 64 + k] : Whh[j * 128 + (k - 64)];
            g_wzp[i] = __float2bfloat16(v);
        }
    }
    // grid barrier (128 blocks, all resident)
    __syncthreads();
    if (tid == 0) {
        unsigned f0 = *((volatile unsigned*)&g_bar_flag);
        __threadfence();
        unsigned old = atomicAdd(&g_bar_count, 1);
        if (old == NBLK - 1) {
            g_bar_count = 0;
            __threadfence();
            atomicAdd(&g_bar_flag, 1);
        } else {
            while (*((volatile unsigned*)&g_bar_flag) == f0) { __nanosleep(64); }
        }
        __threadfence();
    }
    __syncthreads();

    // ======== STAGE 2: s2[b,d,s] into SMEM ========
    {
        float* w2st  = (float*)(smraw + SM_S2_BYTES);  // [32][514] staging (overlaps wihs+floats)
        float* dinst = w2st + 32 * 514;                 // [32][64]
        const int lane = tid & 31, sgrp = tid >> 5;     // sgrp 0..31
        const int d0 = lane * 2, sbase = sgrp * 16;     // 16 s per sgrp

        for (int bb = 0; bb < 2; bb++) {
            const int b = b0 + bb;
            ull acc[2][8];
#pragma unroll
            for (int p = 0; p < 8; p++) {
                float2 bp = *(const float2*)(b2 + sbase + 2 * p);
                acc[0][p] = mk_pair(bp.x, bp.y);
                acc[1][p] = acc[0][p];
            }
            for (int tc = 0; tc < 16; tc++) {
                const int t0 = tc * 32;
                __syncthreads();
                for (int i = tid; i < 32 * 512; i += TPB) {
                    int tt = i & 31, sl = i >> 5;
                    w2st[tt * 514 + sl] = W2[(size_t)sl * TT + t0 + tt];
                }
                for (int i = tid; i < 32 * 64; i += TPB) {
                    int tt = i >> 6, dd = i & 63;
                    dinst[tt * 64 + dd] = din[((size_t)b * TT + t0 + tt) * DD + dd];
                }
                __syncthreads();
#pragma unroll 4
                for (int tt = 0; tt < 32; tt++) {
                    float2 av = *(const float2*)&dinst[tt * 64 + d0];
                    ull ax = mk_pair(av.x, av.x);
                    ull ay = mk_pair(av.y, av.y);
                    const ull* wrow = (const ull*)(w2st + tt * 514 + sbase);
#pragma unroll
                    for (int p = 0; p < 8; p++) {
                        ull wp = wrow[p];
                        ffma2(acc[0][p], wp, ax);
                        ffma2(acc[1][p], wp, ay);
                    }
                }
            }
#pragma unroll
            for (int dl = 0; dl < 2; dl++) {
                unsigned* row = (unsigned*)(s2s + (size_t)(bb * 64 + d0 + dl) * S2STRIDE + sbase);
#pragma unroll
                for (int p = 0; p < 8; p++)
                    row[p] = pack_bf2(pair_lo(acc[dl][p]), pair_hi(acc[dl][p]));
            }
        }
    }
    __syncthreads();

    // ======== STAGE 3: init scan constants ========
    if (tid < 512) {
        w3s[tid] = W3[tid];
        b1s[tid] = b1[tid];
        bzs[tid] = bih[tid] + bhh[tid];
        hc[tid] = 0.f;
    }
    {
        const uint4* src = (const uint4*)g_wzp;  // Wih = kk 0..7
        for (int i = tid; i < 8 * 512; i += TPB) wihs[i] = src[i];
    }
    __syncthreads();
    const float b3v = b3[0];

    // ======== STAGE 4: the scan ========
    for (int t = 0; t < TT; t++) {
        // din prefetch: held in registers of the phase-C warps across A+B
        float dv0 = 0.f, dv1 = 0.f;
        if (tid < 64) {
            const int bb = tid >> 5, lane = tid & 31;
            const float* dp = din + ((size_t)(b0 + bb) * TT + t) * DD;
            dv0 = dp[lane];
            dv1 = dp[lane + 32];
        }

        // ---- Phase A (split-k): s1 partials + zh partials ----
        {
            const int grp = tid >> 9;        // 0: h-half, 1: c-half
            const int s = tid & 511;
            const uint4* w1p = (const uint4*)g_w1p + grp * 16 * 512;
            const uint4* whp = (const uint4*)g_wzp + (8 + grp * 8) * 512;
            const ulonglong2* hb0 = (const ulonglong2*)hc + grp * 32;          // W1 operands b0
            const ulonglong2* hb1 = (const ulonglong2*)(hc + 256) + grp * 32;  // b1
            const ulonglong2* hw0 = (const ulonglong2*)hc + grp * 16;          // Whh operands b0
            const ulonglong2* hw1 = (const ulonglong2*)(hc + 256) + grp * 16;
            ull aW0 = 0, aW1 = 0, aH0 = 0, aH1 = 0;
#pragma unroll 4
            for (int kk = 0; kk < 16; kk++) {
                uint4 w = w1p[kk * 512 + s];
                ulonglong2 pa = hb0[kk * 2], pb = hb0[kk * 2 + 1];
                ulonglong2 qa = hb1[kk * 2], qb = hb1[kk * 2 + 1];
                ull w01 = bfpair(w.x), w23 = bfpair(w.y);
                ull w45 = bfpair(w.z), w67 = bfpair(w.w);
                ffma2(aW0, w01, pa.x); ffma2(aW0, w23, pa.y);
                ffma2(aW0, w45, pb.x); ffma2(aW0, w67, pb.y);
                ffma2(aW1, w01, qa.x); ffma2(aW1, w23, qa.y);
                ffma2(aW1, w45, qb.x); ffma2(aW1, w67, qb.y);
            }
#pragma unroll 4
            for (int kk = 0; kk < 8; kk++) {
                uint4 v = whp[kk * 512 + s];
                ulonglong2 pa = hw0[kk * 2], pb = hw0[kk * 2 + 1];
                ulonglong2 qa = hw1[kk * 2], qb = hw1[kk * 2 + 1];
                ull v01 = bfpair(v.x), v23 = bfpair(v.y);
                ull v45 = bfpair(v.z), v67 = bfpair(v.w);
                ffma2(aH0, v01, pa.x); ffma2(aH0, v23, pa.y);
                ffma2(aH0, v45, pb.x); ffma2(aH0, v67, pb.y);
                ffma2(aH1, v01, qa.x); ffma2(aH1, v23, qa.y);
                ffma2(aH1, v45, qb.x); ffma2(aH1, v67, qb.y);
            }
            if (grp == 0) {
                s1pa[s]       = pair_sum(aW0) + b1s[s];
                s1pa[512 + s] = pair_sum(aW1) + b1s[s];
                zhpa[s]       = pair_sum(aH0) + bzs[s];
                zhpa[512 + s] = pair_sum(aH1) + bzs[s];
            } else {
                s1pb[s]       = pair_sum(aW0);
                s1pb[512 + s] = pair_sum(aW1);
                zhpb[s]       = pair_sum(aH0);
                zhpb[512 + s] = pair_sum(aH1);
            }
        }
        __syncthreads();

        // ---- Phase B: e[b][d] = sum_s tanh(s1a+s1b+s2)*w3 + b3 ----
        {
            const int p = tid >> 3, sub = tid & 7;
            const int bb = p >> 6, d = p & 63;
            const uint4* row = (const uint4*)(s2s + (size_t)(bb * 64 + d) * S2STRIDE);
            const float4* sA = (const float4*)(s1pa + bb * 512);
            const float4* sB = (const float4*)(s1pb + bb * 512);
            const float4* w3v = (const float4*)w3s;
            float acc0 = 0.f, acc1 = 0.f;
#pragma unroll
            for (int i = 0; i < 8; i++) {
                const int q = sub + 8 * i;
                uint4 v = row[q];
                float4 a1 = sA[2 * q], a2 = sA[2 * q + 1];
                float4 c1 = sB[2 * q], c2 = sB[2 * q + 1];
                float4 wA = w3v[2 * q], wB = w3v[2 * q + 1];
                acc0 = fmaf(tanh_fast(a1.x + c1.x + bl(v.x)), wA.x, acc0);
                acc1 = fmaf(tanh_fast(a1.y + c1.y + bh(v.x)), wA.y, acc1);
                acc0 = fmaf(tanh_fast(a1.z + c1.z + bl(v.y)), wA.z, acc0);
                acc1 = fmaf(tanh_fast(a1.w + c1.w + bh(v.y)), wA.w, acc1);
                acc0 = fmaf(tanh_fast(a2.x + c2.x + bl(v.z)), wB.x, acc0);
                acc1 = fmaf(tanh_fast(a2.y + c2.y + bh(v.z)), wB.y, acc1);
                acc0 = fmaf(tanh_fast(a2.z + c2.z + bl(v.w)), wB.z, acc0);
                acc1 = fmaf(tanh_fast(a2.w + c2.w + bh(v.w)), wB.w, acc1);
            }
            float acc = acc0 + acc1;
            acc += __shfl_xor_sync(0xffffffffu, acc, 1);
            acc += __shfl_xor_sync(0xffffffffu, acc, 2);
            acc += __shfl_xor_sync(0xffffffffu, acc, 4);
            if (sub == 0) es[bb * 64 + d] = acc + b3v;
        }
        __syncthreads();

        // ---- Phase C: softmax over d, x = a * x_t ----
        if (tid < 64) {
            const int bb = tid >> 5, lane = tid & 31;
            float e0 = es[bb * 64 + lane], e1 = es[bb * 64 + lane + 32];
            float m = fmaxf(e0, e1);
#pragma unroll
            for (int o = 16; o; o >>= 1) m = fmaxf(m, __shfl_xor_sync(0xffffffffu, m, o));
            float p0 = __expf(e0 - m), p1 = __expf(e1 - m);
            float sm = p0 + p1;
#pragma unroll
            for (int o = 16; o; o >>= 1) sm += __shfl_xor_sync(0xffffffffu, sm, o);
            float inv = 1.f / sm;
            xs[bb * 64 + lane]      = p0 * inv * dv0;
            xs[bb * 64 + lane + 32] = p1 * inv * dv1;
        }
        __syncthreads();

        // ---- Phase D: z[b][j] = x.WihCol + zhpa + zhpb ----
        {
            const int b = tid >> 9, j = tid & 511;
            const ulonglong2* xv = (const ulonglong2*)(xs + b * 64);
            ull a = 0;
#pragma unroll
            for (int kk = 0; kk < 8; kk++) {
                uint4 w = wihs[kk * 512 + j];
                ulonglong2 xa = xv[kk * 2], xb = xv[kk * 2 + 1];
                ffma2(a, bfpair(w.x), xa.x); ffma2(a, bfpair(w.y), xa.y);
                ffma2(a, bfpair(w.z), xb.x); ffma2(a, bfpair(w.w), xb.y);
            }
            zbuf[b * 512 + j] = pair_sum(a) + zhpa[b * 512 + j] + zhpb[b * 512 + j];
        }
        __syncthreads();

        // ---- Phase E: gates, state update, output ----
        if (tid < 256) {
            const int bb = tid >> 7, m = tid & 127;
            float iv = zbuf[bb * 512 + m];
            float fv = zbuf[bb * 512 + 128 + m];
            float gv = zbuf[bb * 512 + 256 + m];
            float ov = zbuf[bb * 512 + 384 + m];
            float c = hc[bb * 256 + 128 + m];
            float cn = sigf(fv) * c + sigf(iv) * tanh_ex(gv);
            float hn = sigf(ov) * tanh_ex(cn);
            hc[bb * 256 + 128 + m] = cn;
            hc[bb * 256 + m] = hn;
            out[(((size_t)(b0 + bb)) * TT + t) * HH + m] = hn;
        }
        __syncthreads();
    }
}

// ---------------- launch ----------------
extern "C" void kernel_launch(void* const* d_in, const int* in_sizes, int n_in,
                              void* d_out, int out_size) {
    const float* din = (const float*)d_in[0];
    const float* Wih = (const float*)d_in[1];
    const float* Whh = (const float*)d_in[2];
    const float* bih = (const float*)d_in[3];
    const float* bhh = (const float*)d_in[4];
    const float* W1  = (const float*)d_in[5];
    const float* b1  = (const float*)d_in[6];
    const float* W2  = (const float*)d_in[7];
    const float* b2  = (const float*)d_in[8];
    const float* W3  = (const float*)d_in[9];
    const float* b3  = (const float*)d_in[10];
    float* out = (float*)d_out;

    cudaFuncSetAttribute(fused_kernel, cudaFuncAttributeMaxDynamicSharedMemorySize, SM_TOTAL);
    fused_kernel<<<NBLK, TPB, SM_TOTAL>>>(din, Wih, Whh, bih, bhh, W1, b1, W2, b2, W3, b3, out);
}

// round 8
// speedup vs baseline: 1.6164x; 1.6164x over previous
#include <cuda_runtime.h>
#include <cuda_bf16.h>

#define BB 256
#define TT 512
#define DD 64
#define HH 128
#define NBLK 128

// ---------------- device scratch (static, no allocation) ----------------
__device__ __nv_bfloat16 g_w1p[32 * 512 * 8];   // [kk][s][u], k = kk*8+u in [0,256)
__device__ __nv_bfloat16 g_wzp[24 * 512 * 8];   // [kk][j][u], k' in [0,192): 0..63 Wih, 64..191 Whh
__device__ unsigned g_bar_count = 0;
__device__ unsigned g_bar_flag = 0;

// ---------------- helpers ----------------
typedef unsigned long long ull;

__device__ __forceinline__ float tanh_fast(float x) {
    float y;
    asm("tanh.approx.f32 %0, %1;" : "=f"(y) : "f"(x));
    return y;
}
__device__ __forceinline__ float sigf(float x) { return 1.f / (1.f + __expf(-x)); }
__device__ __forceinline__ float tanh_ex(float x) {
    x = fminf(fmaxf(x, -15.f), 15.f);
    float e = __expf(2.f * x);
    return (e - 1.f) / (e + 1.f);
}
__device__ __forceinline__ unsigned pack_bf2(float a, float b) {
    __nv_bfloat162 t = __floats2bfloat162_rn(a, b);
    return *(unsigned*)&t;
}
__device__ __forceinline__ float bl(unsigned u) { return __uint_as_float(u << 16); }
__device__ __forceinline__ float bh(unsigned u) { return __uint_as_float(u & 0xffff0000u); }
__device__ __forceinline__ void ffma2(ull& acc, ull ab, ull cd) {
    asm("fma.rn.f32x2 %0, %1, %2, %0;" : "+l"(acc) : "l"(ab), "l"(cd));
}
__device__ __forceinline__ ull bfpair(unsigned u) {
    ull p;
    asm("{\n\t.reg .b32 lo, hi;\n\t"
        "shl.b32 lo, %1, 16;\n\t"
        "and.b32 hi, %1, 0xff" "ff0000;\n\t"
        "mov.b64 %0, {lo, hi};\n\t}" : "=l"(p) : "r"(u));
    return p;
}
__device__ __forceinline__ ull mk_pair(float lo, float hi) {
    ull p;
    asm("mov.b64 %0, {%1, %2};" : "=l"(p) : "f"(lo), "f"(hi));
    return p;
}
__device__ __forceinline__ float pair_lo(ull p) { return __uint_as_float((unsigned)p); }
__device__ __forceinline__ float pair_hi(ull p) { return __uint_as_float((unsigned)(p >> 32)); }
__device__ __forceinline__ float pair_sum(ull p) { return pair_lo(p) + pair_hi(p); }

// ---------------- smem layout ----------------
#define S2STRIDE 552
#define SM_S2_BYTES (2 * 64 * S2STRIDE * 2)      // 141312
#define SM_WIH_BYTES (8 * 512 * 16)              // 65536
#define SM_FLOATS (512 + 1024 + 1024 + 128 + 128 + 512 + 512 + 512 + 128)  // 4480
#define SM_TOTAL (SM_S2_BYTES + SM_WIH_BYTES + SM_FLOATS * 4)              // 224768

// ---------------- the one kernel ----------------
__global__ void __launch_bounds__(512, 1) fused_kernel(
    const float* __restrict__ din, const float* __restrict__ Wih,
    const float* __restrict__ Whh, const float* __restrict__ bih,
    const float* __restrict__ bhh, const float* __restrict__ W1,
    const float* __restrict__ b1, const float* __restrict__ W2,
    const float* __restrict__ b2, const float* __restrict__ W3,
    const float* __restrict__ b3, float* __restrict__ out) {
    extern __shared__ char smraw[];
    __nv_bfloat16* s2s = (__nv_bfloat16*)smraw;                 // [2*64][552]
    uint4* wihs = (uint4*)(smraw + SM_S2_BYTES);                // [8*512] uint4
    float* hc   = (float*)(smraw + SM_S2_BYTES + SM_WIH_BYTES); // [2][256] : h then c
    float* s1s  = hc + 512;                                      // [2][512]
    float* zhs  = s1s + 1024;                                    // [2][512]
    float* xs   = zhs + 1024;                                    // [2][64]
    float* es   = xs + 128;                                      // [2][64]
    float* w3s  = es + 128;                                      // [512]
    float* b1s  = w3s + 512;                                     // [512]
    float* bzs  = b1s + 512;                                     // [512]
    float* dinb = bzs + 512;                                     // [2][64]

    const int tid = threadIdx.x;
    const int b0 = blockIdx.x * 2;

    // ======== STAGE 1: pack weights (grid-strided) ========
    {
        int gidx = blockIdx.x * 512 + tid;
        int gstride = NBLK * 512;
        for (int i = gidx; i < 32 * 512 * 8; i += gstride) {
            int u = i & 7, s = (i >> 3) & 511, kk = i >> 12;
            g_w1p[i] = __float2bfloat16(W1[s * 256 + kk * 8 + u]);
        }
        for (int i = gidx; i < 24 * 512 * 8; i += gstride) {
            int u = i & 7, j = (i >> 3) & 511, kk = i >> 12;
            int k = kk * 8 + u;
            float v = (k < 64) ? Wih[j * 64 + k] : Whh[j * 128 + (k - 64)];
            g_wzp[i] = __float2bfloat16(v);
        }
    }
    // grid barrier (128 blocks, all resident)
    __syncthreads();
    if (tid == 0) {
        unsigned f0 = *((volatile unsigned*)&g_bar_flag);
        __threadfence();
        unsigned old = atomicAdd(&g_bar_count, 1);
        if (old == NBLK - 1) {
            g_bar_count = 0;
            __threadfence();
            atomicAdd(&g_bar_flag, 1);
        } else {
            while (*((volatile unsigned*)&g_bar_flag) == f0) { __nanosleep(64); }
        }
        __threadfence();
    }
    __syncthreads();

    // ======== STAGE 2: s2[b,d,s] into SMEM ========
    {
        float* w2st  = (float*)(smraw + SM_S2_BYTES);  // [32][514] staging
        float* dinst = w2st + 32 * 514;                 // [32][64]
        const int lane = tid & 31, sgrp = tid >> 5;
        const int d0 = lane * 2, sbase = sgrp * 32;

        for (int bb = 0; bb < 2; bb++) {
            const int b = b0 + bb;
            ull acc[2][16];
#pragma unroll
            for (int p = 0; p < 16; p++) {
                float2 bp = *(const float2*)(b2 + sbase + 2 * p);
                acc[0][p] = mk_pair(bp.x, bp.y);
                acc[1][p] = acc[0][p];
            }
            for (int tc = 0; tc < 16; tc++) {
                const int t0 = tc * 32;
                __syncthreads();
                for (int i = tid; i < 32 * 512; i += 512) {
                    int tt = i & 31, sl = i >> 5;
                    w2st[tt * 514 + sl] = W2[(size_t)sl * TT + t0 + tt];
                }
                for (int i = tid; i < 32 * 64; i += 512) {
                    int tt = i >> 6, dd = i & 63;
                    dinst[tt * 64 + dd] = din[((size_t)b * TT + t0 + tt) * DD + dd];
                }
                __syncthreads();
#pragma unroll 4
                for (int tt = 0; tt < 32; tt++) {
                    float2 av = *(const float2*)&dinst[tt * 64 + d0];
                    ull ax = mk_pair(av.x, av.x);
                    ull ay = mk_pair(av.y, av.y);
                    const ull* wrow = (const ull*)(w2st + tt * 514 + sbase);
#pragma unroll
                    for (int p = 0; p < 16; p++) {
                        ull wp = wrow[p];
                        ffma2(acc[0][p], wp, ax);
                        ffma2(acc[1][p], wp, ay);
                    }
                }
            }
#pragma unroll
            for (int dl = 0; dl < 2; dl++) {
                unsigned* row = (unsigned*)(s2s + (size_t)(bb * 64 + d0 + dl) * S2STRIDE + sbase);
#pragma unroll
                for (int p = 0; p < 16; p++)
                    row[p] = pack_bf2(pair_lo(acc[dl][p]), pair_hi(acc[dl][p]));
            }
        }
    }
    __syncthreads();

    // ======== STAGE 3: init scan constants ========
    w3s[tid] = W3[tid];
    b1s[tid] = b1[tid];
    bzs[tid] = bih[tid] + bhh[tid];
    hc[tid] = 0.f;
    {
        const uint4* src = (const uint4*)g_wzp;  // Wih = kk 0..7
        for (int i = tid; i < 8 * 512; i += 512) wihs[i] = src[i];
    }
    __syncthreads();
    const float b3v = b3[0];

    // ======== STAGE 4: the scan ========
    for (int t = 0; t < TT; t++) {
        // prefetch din[., t, .] for phase C (latency hidden behind phase A)
        float dval = 0.f;
        if (tid < 128) {
            int bb = tid >> 6, dd = tid & 63;
            dval = din[((size_t)(b0 + bb) * TT + t) * DD + dd];
        }
        // ---- Phase A: s1 = [h;c].W1col + b1 ; zh = h.WhhCol + bz ----
        {
            const int s = tid;
            const uint4* w1p = (const uint4*)g_w1p;
            const uint4* whp = (const uint4*)g_wzp + 8 * 512;
            const ulonglong2* h0 = (const ulonglong2*)hc;
            const ulonglong2* h1 = (const ulonglong2*)(hc + 256);
            ull aW0 = 0, aW1 = 0, aH0 = 0, aH1 = 0;
#pragma unroll 4
            for (int kk = 0; kk < 16; kk++) {
                uint4 w = w1p[kk * 512 + s];
                uint4 v = whp[kk * 512 + s];
                ulonglong2 pa = h0[kk * 2], pb = h0[kk * 2 + 1];
                ulonglong2 qa = h1[kk * 2], qb = h1[kk * 2 + 1];
                ull w01 = bfpair(w.x), w23 = bfpair(w.y);
                ull w45 = bfpair(w.z), w67 = bfpair(w.w);
                ull v01 = bfpair(v.x), v23 = bfpair(v.y);
                ull v45 = bfpair(v.z), v67 = bfpair(v.w);
                ffma2(aW0, w01, pa.x); ffma2(aW0, w23, pa.y);
                ffma2(aW0, w45, pb.x); ffma2(aW0, w67, pb.y);
                ffma2(aW1, w01, qa.x); ffma2(aW1, w23, qa.y);
                ffma2(aW1, w45, qb.x); ffma2(aW1, w67, qb.y);
                ffma2(aH0, v01, pa.x); ffma2(aH0, v23, pa.y);
                ffma2(aH0, v45, pb.x); ffma2(aH0, v67, pb.y);
                ffma2(aH1, v01, qa.x); ffma2(aH1, v23, qa.y);
                ffma2(aH1, v45, qb.x); ffma2(aH1, v67, qb.y);
            }
#pragma unroll 4
            for (int kk = 16; kk < 32; kk++) {
                uint4 w = w1p[kk * 512 + s];
                ulonglong2 pa = h0[kk * 2], pb = h0[kk * 2 + 1];
                ulonglong2 qa = h1[kk * 2], qb = h1[kk * 2 + 1];
                ull w01 = bfpair(w.x), w23 = bfpair(w.y);
                ull w45 = bfpair(w.z), w67 = bfpair(w.w);
                ffma2(aW0, w01, pa.x); ffma2(aW0, w23, pa.y);
                ffma2(aW0, w45, pb.x); ffma2(aW0, w67, pb.y);
                ffma2(aW1, w01, qa.x); ffma2(aW1, w23, qa.y);
                ffma2(aW1, w45, qb.x); ffma2(aW1, w67, qb.y);
            }
            s1s[s]       = pair_sum(aW0) + b1s[s];
            s1s[512 + s] = pair_sum(aW1) + b1s[s];
            zhs[s]       = pair_sum(aH0) + bzs[s];
            zhs[512 + s] = pair_sum(aH1) + bzs[s];
        }
        if (tid < 128) dinb[tid] = dval;
        __syncthreads();

        // ---- Phase B: e[b][d] = sum_s tanh(s1+s2)*w3 + b3 ----
        // 16 subs x 4 rows per group: s1/w3 loads amortized over 4 d-rows.
        {
            const int sub = tid & 15, grp = tid >> 4;      // grp 0..31
            const int bb = grp >> 4, d0 = (grp & 15) * 4;  // 4 rows per group
            const __nv_bfloat16* rowbase = s2s + (size_t)(bb * 64 + d0) * S2STRIDE;
            const uint4* r0 = (const uint4*)(rowbase);
            const uint4* r1 = (const uint4*)(rowbase + S2STRIDE);
            const uint4* r2 = (const uint4*)(rowbase + 2 * S2STRIDE);
            const uint4* r3 = (const uint4*)(rowbase + 3 * S2STRIDE);
            const float4* s1f = (const float4*)(s1s + bb * 512);
            const float4* w3f = (const float4*)w3s;
            float a0 = 0.f, a1 = 0.f, a2 = 0.f, a3 = 0.f;
#pragma unroll
            for (int i = 0; i < 4; i++) {
                const int q = sub + 16 * i;
                float4 sA = s1f[2 * q], sB = s1f[2 * q + 1];
                float4 wA = w3f[2 * q], wB = w3f[2 * q + 1];
                uint4 v0 = r0[q], v1 = r1[q], v2 = r2[q], v3 = r3[q];
                a0 = fmaf(tanh_fast(sA.x + bl(v0.x)), wA.x, a0);
                a0 = fmaf(tanh_fast(sA.y + bh(v0.x)), wA.y, a0);
                a0 = fmaf(tanh_fast(sA.z + bl(v0.y)), wA.z, a0);
                a0 = fmaf(tanh_fast(sA.w + bh(v0.y)), wA.w, a0);
                a0 = fmaf(tanh_fast(sB.x + bl(v0.z)), wB.x, a0);
                a0 = fmaf(tanh_fast(sB.y + bh(v0.z)), wB.y, a0);
                a0 = fmaf(tanh_fast(sB.z + bl(v0.w)), wB.z, a0);
                a0 = fmaf(tanh_fast(sB.w + bh(v0.w)), wB.w, a0);
                a1 = fmaf(tanh_fast(sA.x + bl(v1.x)), wA.x, a1);
                a1 = fmaf(tanh_fast(sA.y + bh(v1.x)), wA.y, a1);
                a1 = fmaf(tanh_fast(sA.z + bl(v1.y)), wA.z, a1);
                a1 = fmaf(tanh_fast(sA.w + bh(v1.y)), wA.w, a1);
                a1 = fmaf(tanh_fast(sB.x + bl(v1.z)), wB.x, a1);
                a1 = fmaf(tanh_fast(sB.y + bh(v1.z)), wB.y, a1);
                a1 = fmaf(tanh_fast(sB.z + bl(v1.w)), wB.z, a1);
                a1 = fmaf(tanh_fast(sB.w + bh(v1.w)), wB.w, a1);
                a2 = fmaf(tanh_fast(sA.x + bl(v2.x)), wA.x, a2);
                a2 = fmaf(tanh_fast(sA.y + bh(v2.x)), wA.y, a2);
                a2 = fmaf(tanh_fast(sA.z + bl(v2.y)), wA.z, a2);
                a2 = fmaf(tanh_fast(sA.w + bh(v2.y)), wA.w, a2);
                a2 = fmaf(tanh_fast(sB.x + bl(v2.z)), wB.x, a2);
                a2 = fmaf(tanh_fast(sB.y + bh(v2.z)), wB.y, a2);
                a2 = fmaf(tanh_fast(sB.z + bl(v2.w)), wB.z, a2);
                a2 = fmaf(tanh_fast(sB.w + bh(v2.w)), wB.w, a2);
                a3 = fmaf(tanh_fast(sA.x + bl(v3.x)), wA.x, a3);
                a3 = fmaf(tanh_fast(sA.y + bh(v3.x)), wA.y, a3);
                a3 = fmaf(tanh_fast(sA.z + bl(v3.y)), wA.z, a3);
                a3 = fmaf(tanh_fast(sA.w + bh(v3.y)), wA.w, a3);
                a3 = fmaf(tanh_fast(sB.x + bl(v3.z)), wB.x, a3);
                a3 = fmaf(tanh_fast(sB.y + bh(v3.z)), wB.y, a3);
                a3 = fmaf(tanh_fast(sB.z + bl(v3.w)), wB.z, a3);
                a3 = fmaf(tanh_fast(sB.w + bh(v3.w)), wB.w, a3);
            }
#pragma unroll
            for (int o = 1; o < 16; o <<= 1) {
                a0 += __shfl_xor_sync(0xffffffffu, a0, o);
                a1 += __shfl_xor_sync(0xffffffffu, a1, o);
                a2 += __shfl_xor_sync(0xffffffffu, a2, o);
                a3 += __shfl_xor_sync(0xffffffffu, a3, o);
            }
            if (sub == 0) {
                es[bb * 64 + d0 + 0] = a0 + b3v;
                es[bb * 64 + d0 + 1] = a1 + b3v;
                es[bb * 64 + d0 + 2] = a2 + b3v;
                es[bb * 64 + d0 + 3] = a3 + b3v;
            }
        }
        __syncthreads();

        // ---- Phase C: softmax over d, x = a * x_t ----
        if (tid < 64) {
            const int bb = tid >> 5, lane = tid & 31;
            float e0 = es[bb * 64 + lane], e1 = es[bb * 64 + lane + 32];
            float m = fmaxf(e0, e1);
#pragma unroll
            for (int o = 16; o; o >>= 1) m = fmaxf(m, __shfl_xor_sync(0xffffffffu, m, o));
            float p0 = __expf(e0 - m), p1 = __expf(e1 - m);
            float sm = p0 + p1;
#pragma unroll
            for (int o = 16; o; o >>= 1) sm += __shfl_xor_sync(0xffffffffu, sm, o);
            float inv = 1.f / sm;
            xs[bb * 64 + lane]      = p0 * inv * dinb[bb * 64 + lane];
            xs[bb * 64 + lane + 32] = p1 * inv * dinb[bb * 64 + lane + 32];
        }
        __syncthreads();

        // ---- Phase D: z += x.WihCol (weights from SMEM) ----
        {
            const int j = tid;
            const ulonglong2* x0 = (const ulonglong2*)xs;
            const ulonglong2* x1 = (const ulonglong2*)(xs + 64);
            ull a0 = 0, a1 = 0;
#pragma unroll
            for (int kk = 0; kk < 8; kk++) {
                uint4 w = wihs[kk * 512 + j];
                ulonglong2 pa = x0[kk * 2], pb = x0[kk * 2 + 1];
                ulonglong2 qa = x1[kk * 2], qb = x1[kk * 2 + 1];
                ull w01 = bfpair(w.x), w23 = bfpair(w.y);
                ull w45 = bfpair(w.z), w67 = bfpair(w.w);
                ffma2(a0, w01, pa.x); ffma2(a0, w23, pa.y);
                ffma2(a0, w45, pb.x); ffma2(a0, w67, pb.y);
                ffma2(a1, w01, qa.x); ffma2(a1, w23, qa.y);
                ffma2(a1, w45, qb.x); ffma2(a1, w67, qb.y);
            }
            zhs[j]       += pair_sum(a0);
            zhs[512 + j] += pair_sum(a1);
        }
        __syncthreads();

        // ---- Phase E: gates, state update, output ----
        if (tid < 256) {
            const int bb = tid >> 7, m = tid & 127;
            float iv = zhs[bb * 512 + m];
            float fv = zhs[bb * 512 + 128 + m];
            float gv = zhs[bb * 512 + 256 + m];
            float ov = zhs[bb * 512 + 384 + m];
            float c = hc[bb * 256 + 128 + m];
            float cn = sigf(fv) * c + sigf(iv) * tanh_ex(gv);
            float hn = sigf(ov) * tanh_ex(cn);
            hc[bb * 256 + 128 + m] = cn;
            hc[bb * 256 + m] = hn;
            out[(((size_t)(b0 + bb)) * TT + t) * HH + m] = hn;
        }
        __syncthreads();
    }
}

// ---------------- launch ----------------
extern "C" void kernel_launch(void* const* d_in, const int* in_sizes, int n_in,
                              void* d_out, int out_size) {
    const float* din = (const float*)d_in[0];
    const float* Wih = (const float*)d_in[1];
    const float* Whh = (const float*)d_in[2];
    const float* bih = (const float*)d_in[3];
    const float* bhh = (const float*)d_in[4];
    const float* W1  = (const float*)d_in[5];
    const float* b1  = (const float*)d_in[6];
    const float* W2  = (const float*)d_in[7];
    const float* b2  = (const float*)d_in[8];
    const float* W3  = (const float*)d_in[9];
    const float* b3  = (const float*)d_in[10];
    float* out = (float*)d_out;

    cudaFuncSetAttribute(fused_kernel, cudaFuncAttributeMaxDynamicSharedMemorySize, SM_TOTAL);
    fused_kernel<<<NBLK, 512, SM_TOTAL>>>(din, Wih, Whh, bih, bhh, W1, b1, W2, b2, W3, b3, out);
}